// round 3
// baseline (speedup 1.0000x reference)
#include <cuda_runtime.h>
#include <math.h>

// Problem constants
#define BSZ 256     // batch
#define TT  512     // time steps
#define EE  256     // embedding dim
#define HH  256     // hidden dim
#define KH  512     // E + H
#define G3  768     // 3 * H (z, r, m)

// Scratch (device globals: allocation-free rule)
__device__ float g_WT[KH * G3];                    // transposed weights: WT[k][g*H + j] = W_g[j][k]
__device__ float g_bias[G3];
__device__ float g_Gx[(size_t)BSZ * TT * G3];      // precomputed x-part + bias, layout [t][b][3H]

// ---------------------------------------------------------------------------
// Kernel 1: weight transpose + bias concat
// ---------------------------------------------------------------------------
__global__ void prep_kernel(const float* __restrict__ Wz, const float* __restrict__ bz,
                            const float* __restrict__ Wr, const float* __restrict__ br,
                            const float* __restrict__ Wm, const float* __restrict__ bm) {
    int idx = blockIdx.x * blockDim.x + threadIdx.x;
    if (idx < KH * G3) {
        int k  = idx / G3;
        int gj = idx - k * G3;
        int g  = gj >> 8;
        int jj = gj & 255;
        const float* W = (g == 0) ? Wz : (g == 1) ? Wr : Wm;
        g_WT[idx] = W[jj * KH + k];
    }
    if (idx < G3) {
        int g  = idx >> 8;
        int jj = idx & 255;
        const float* bb = (g == 0) ? bz : (g == 1) ? br : bm;
        g_bias[idx] = bb[jj];
    }
}

// ---------------------------------------------------------------------------
// Kernel 2: Gx[t][b][gj] = emb[b][t][:] . WT[:E][gj] + bias[gj]
// Tiled fp32 GEMM: M = T*B (m = t*256 + b), N = 768, K = 256
// 128x128 tile, BK=8, 256 threads, 8x8 microtile per thread
// ---------------------------------------------------------------------------
#define BM 128
#define BN 128
#define BK 8

__global__ __launch_bounds__(256) void gemm_x_kernel(const float* __restrict__ emb) {
    __shared__ float As[BK][BM];
    __shared__ float Bs[BK][BN];

    int tid = threadIdx.x;
    int m0 = blockIdx.y * BM;
    int n0 = blockIdx.x * BN;

    int tx = tid & 15;        // 0..15 -> N microtile
    int ty = tid >> 4;        // 0..15 -> M microtile

    // A tile load mapping: 128 rows x 8 k, one float4 per thread
    int arow = tid >> 1;           // 0..127
    int akq  = (tid & 1) << 2;     // 0 or 4
    int m    = m0 + arow;
    int bidx = m & (BSZ - 1);      // m = t*256 + b
    int tidx = m >> 8;
    const float* aptr = emb + ((size_t)bidx * TT + tidx) * EE + akq;

    // B tile load mapping: 8 rows x 128 n, one float4 per thread
    int bkr = tid >> 5;            // 0..7
    int bnq = (tid & 31) << 2;     // 0..124
    const float* bptr = g_WT + (size_t)bkr * G3 + n0 + bnq;

    float acc[8][8];
#pragma unroll
    for (int i = 0; i < 8; i++)
#pragma unroll
        for (int jj = 0; jj < 8; jj++) acc[i][jj] = 0.f;

    for (int k0 = 0; k0 < EE; k0 += BK) {
        float4 av = *(const float4*)(aptr + k0);
        float4 bv = *(const float4*)(bptr + (size_t)k0 * G3);

        As[akq + 0][arow] = av.x;
        As[akq + 1][arow] = av.y;
        As[akq + 2][arow] = av.z;
        As[akq + 3][arow] = av.w;
        *(float4*)(&Bs[bkr][bnq]) = bv;
        __syncthreads();

#pragma unroll
        for (int kk = 0; kk < BK; kk++) {
            float a[8], b[8];
            *(float4*)(a)     = *(const float4*)(&As[kk][ty * 8]);
            *(float4*)(a + 4) = *(const float4*)(&As[kk][ty * 8 + 4]);
            *(float4*)(b)     = *(const float4*)(&Bs[kk][tx * 8]);
            *(float4*)(b + 4) = *(const float4*)(&Bs[kk][tx * 8 + 4]);
#pragma unroll
            for (int i = 0; i < 8; i++)
#pragma unroll
                for (int jj = 0; jj < 8; jj++)
                    acc[i][jj] = fmaf(a[i], b[jj], acc[i][jj]);
        }
        __syncthreads();
    }

    float biasv[8];
    *(float4*)(biasv)     = *(const float4*)(&g_bias[n0 + tx * 8]);
    *(float4*)(biasv + 4) = *(const float4*)(&g_bias[n0 + tx * 8 + 4]);

#pragma unroll
    for (int i = 0; i < 8; i++) {
        int mm = m0 + ty * 8 + i;
        float* gp = g_Gx + (size_t)mm * G3 + n0 + tx * 8;
        float4 v0, v1;
        v0.x = acc[i][0] + biasv[0]; v0.y = acc[i][1] + biasv[1];
        v0.z = acc[i][2] + biasv[2]; v0.w = acc[i][3] + biasv[3];
        v1.x = acc[i][4] + biasv[4]; v1.y = acc[i][5] + biasv[5];
        v1.z = acc[i][6] + biasv[6]; v1.w = acc[i][7] + biasv[7];
        *(float4*)(gp)     = v0;
        *(float4*)(gp + 4) = v1;
    }
}

// ---------------------------------------------------------------------------
// Kernel 3: recurrent part. 64 CTAs x 256 threads, 4 batches per CTA.
// Thread j owns hidden unit j for its 4 batches. Batch rows are fully
// independent -> no cross-CTA sync, whole T loop inside one kernel.
// ---------------------------------------------------------------------------
__device__ __forceinline__ float sigmoidf_(float x) {
    return 1.f / (1.f + __expf(-x));
}

__global__ __launch_bounds__(256) void gru_rec_kernel(float* __restrict__ out) {
    __shared__ float hs[4][HH];
    __shared__ float rhs[4][HH];

    int j  = threadIdx.x;
    int b0 = blockIdx.x * 4;

#pragma unroll
    for (int b = 0; b < 4; b++) hs[b][j] = 0.f;
    __syncthreads();

    // recurrent weight rows (k in [E, E+H)), column g*H + j
    const float* Wp = g_WT + (size_t)EE * G3 + j;

    for (int t = 0; t < TT; t++) {
        const float* gx = g_Gx + ((size_t)t * BSZ + b0) * G3 + j;

        float accZ[4], accR[4];
#pragma unroll
        for (int b = 0; b < 4; b++) {
            accZ[b] = gx[(size_t)b * G3];
            accR[b] = gx[(size_t)b * G3 + HH];
        }

#pragma unroll 4
        for (int k = 0; k < HH; k++) {
            float wz = Wp[(size_t)k * G3];
            float wr = Wp[(size_t)k * G3 + HH];
#pragma unroll
            for (int b = 0; b < 4; b++) {
                float h = hs[b][k];
                accZ[b] = fmaf(wz, h, accZ[b]);
                accR[b] = fmaf(wr, h, accR[b]);
            }
        }

        float zb[4], hold[4];
#pragma unroll
        for (int b = 0; b < 4; b++) {
            float z = sigmoidf_(accZ[b]);
            float r = sigmoidf_(accR[b]);
            hold[b] = hs[b][j];
            rhs[b][j] = r * hold[b];
            zb[b] = z;
        }
        __syncthreads();   // rhs published, all hs reads of phase A done

        float accM[4];
#pragma unroll
        for (int b = 0; b < 4; b++) accM[b] = gx[(size_t)b * G3 + 2 * HH];

#pragma unroll 4
        for (int k = 0; k < HH; k++) {
            float wm = Wp[(size_t)k * G3 + 2 * HH];
#pragma unroll
            for (int b = 0; b < 4; b++)
                accM[b] = fmaf(wm, rhs[b][k], accM[b]);
        }

#pragma unroll
        for (int b = 0; b < 4; b++) {
            float hc = tanhf(accM[b]);
            float hn = fmaf(zb[b], hc - hold[b], hold[b]);   // (1-z)h + z*hc
            hs[b][j] = hn;
            out[((size_t)(b0 + b) * TT + t) * HH + j] = hn;
        }
        __syncthreads();   // hs published for next step, rhs reads done
    }
}

// ---------------------------------------------------------------------------
// Launch
// ---------------------------------------------------------------------------
extern "C" void kernel_launch(void* const* d_in, const int* in_sizes, int n_in,
                              void* d_out, int out_size) {
    const float* emb = (const float*)d_in[0];
    const float* Wz  = (const float*)d_in[1];
    const float* bz  = (const float*)d_in[2];
    const float* Wr  = (const float*)d_in[3];
    const float* br  = (const float*)d_in[4];
    const float* Wm  = (const float*)d_in[5];
    const float* bm  = (const float*)d_in[6];
    float* out = (float*)d_out;

    prep_kernel<<<(KH * G3 + 255) / 256, 256>>>(Wz, bz, Wr, br, Wm, bm);
    gemm_x_kernel<<<dim3(G3 / BN, (BSZ * TT) / BM), 256>>>(emb);
    gru_rec_kernel<<<BSZ / 4, 256>>>(out);
}

// round 4
// speedup vs baseline: 1.0822x; 1.0822x over previous
#include <cuda_runtime.h>
#include <math.h>

// Problem constants
#define BSZ 256     // batch
#define TT  512     // time steps
#define EE  256     // embedding dim
#define HH  256     // hidden dim
#define KH  512     // E + H
#define G3  768     // 3 * H (z, r, m)

// Scratch (device globals: allocation-free rule)
__device__ float  g_WT[KH * G3];                   // transposed weights (GEMM uses rows k<EE)
__device__ float  g_bias[G3];
__device__ float2 g_Wzr[HH * HH];                  // recurrent z/r interleaved: [k][j] -> (Wz[j][E+k], Wr[j][E+k])
__device__ float  g_Wm2[HH * HH];                  // recurrent m:               [k][j] ->  Wm[j][E+k]
__device__ float  g_Gx[(size_t)BSZ * TT * G3];     // precomputed x-part + bias, layout [t][b][3H]

// ---------------------------------------------------------------------------
// Kernel 1: weight transpose + bias concat + recurrent repack
// ---------------------------------------------------------------------------
__global__ void prep_kernel(const float* __restrict__ Wz, const float* __restrict__ bz,
                            const float* __restrict__ Wr, const float* __restrict__ br,
                            const float* __restrict__ Wm, const float* __restrict__ bm) {
    int idx = blockIdx.x * blockDim.x + threadIdx.x;
    if (idx < KH * G3) {
        int k  = idx / G3;
        int gj = idx - k * G3;
        int g  = gj >> 8;
        int jj = gj & 255;
        const float* W = (g == 0) ? Wz : (g == 1) ? Wr : Wm;
        g_WT[idx] = W[jj * KH + k];
    }
    if (idx < HH * HH) {                 // recurrent repack (k = reduction idx, j = unit)
        int k = idx >> 8;
        int j = idx & 255;
        g_Wzr[idx] = make_float2(Wz[j * KH + EE + k], Wr[j * KH + EE + k]);
        g_Wm2[idx] = Wm[j * KH + EE + k];
    }
    if (idx < G3) {
        int g  = idx >> 8;
        int jj = idx & 255;
        const float* bb = (g == 0) ? bz : (g == 1) ? br : bm;
        g_bias[idx] = bb[jj];
    }
}

// ---------------------------------------------------------------------------
// Kernel 2: Gx[t][b][gj] = emb[b][t][:] . WT[:E][gj] + bias[gj]
// Tiled fp32 GEMM: M = T*B (m = t*256 + b), N = 768, K = 256
// ---------------------------------------------------------------------------
#define BM 128
#define BN 128
#define BK 8

__global__ __launch_bounds__(256) void gemm_x_kernel(const float* __restrict__ emb) {
    __shared__ float As[BK][BM];
    __shared__ float Bs[BK][BN];

    int tid = threadIdx.x;
    int m0 = blockIdx.y * BM;
    int n0 = blockIdx.x * BN;

    int tx = tid & 15;
    int ty = tid >> 4;

    int arow = tid >> 1;
    int akq  = (tid & 1) << 2;
    int m    = m0 + arow;
    int bidx = m & (BSZ - 1);
    int tidx = m >> 8;
    const float* aptr = emb + ((size_t)bidx * TT + tidx) * EE + akq;

    int bkr = tid >> 5;
    int bnq = (tid & 31) << 2;
    const float* bptr = g_WT + (size_t)bkr * G3 + n0 + bnq;

    float acc[8][8];
#pragma unroll
    for (int i = 0; i < 8; i++)
#pragma unroll
        for (int jj = 0; jj < 8; jj++) acc[i][jj] = 0.f;

    for (int k0 = 0; k0 < EE; k0 += BK) {
        float4 av = *(const float4*)(aptr + k0);
        float4 bv = *(const float4*)(bptr + (size_t)k0 * G3);

        As[akq + 0][arow] = av.x;
        As[akq + 1][arow] = av.y;
        As[akq + 2][arow] = av.z;
        As[akq + 3][arow] = av.w;
        *(float4*)(&Bs[bkr][bnq]) = bv;
        __syncthreads();

#pragma unroll
        for (int kk = 0; kk < BK; kk++) {
            float a[8], b[8];
            *(float4*)(a)     = *(const float4*)(&As[kk][ty * 8]);
            *(float4*)(a + 4) = *(const float4*)(&As[kk][ty * 8 + 4]);
            *(float4*)(b)     = *(const float4*)(&Bs[kk][tx * 8]);
            *(float4*)(b + 4) = *(const float4*)(&Bs[kk][tx * 8 + 4]);
#pragma unroll
            for (int i = 0; i < 8; i++)
#pragma unroll
                for (int jj = 0; jj < 8; jj++)
                    acc[i][jj] = fmaf(a[i], b[jj], acc[i][jj]);
        }
        __syncthreads();
    }

    float biasv[8];
    *(float4*)(biasv)     = *(const float4*)(&g_bias[n0 + tx * 8]);
    *(float4*)(biasv + 4) = *(const float4*)(&g_bias[n0 + tx * 8 + 4]);

#pragma unroll
    for (int i = 0; i < 8; i++) {
        int mm = m0 + ty * 8 + i;
        float* gp = g_Gx + (size_t)mm * G3 + n0 + tx * 8;
        float4 v0, v1;
        v0.x = acc[i][0] + biasv[0]; v0.y = acc[i][1] + biasv[1];
        v0.z = acc[i][2] + biasv[2]; v0.w = acc[i][3] + biasv[3];
        v1.x = acc[i][4] + biasv[4]; v1.y = acc[i][5] + biasv[5];
        v1.z = acc[i][6] + biasv[6]; v1.w = acc[i][7] + biasv[7];
        *(float4*)(gp)     = v0;
        *(float4*)(gp + 4) = v1;
    }
}

// ---------------------------------------------------------------------------
// Kernel 3: recurrent part. 64 CTAs x 256 threads, 4 batches per CTA.
// Thread j owns hidden unit j for its 4 batches.
// h and r*h stored batch-minor as float4 -> 1 broadcast LDS.128 per k.
// Weights repacked: phase A reads one LDG.64 per k, phase B one LDG.32 per k.
// ---------------------------------------------------------------------------
__device__ __forceinline__ float fast_sigmoid(float x) {
    float e = __expf(-x);
    return __fdividef(1.f, 1.f + e);
}
__device__ __forceinline__ float fast_tanh(float x) {
    float e = __expf(2.f * x);
    return __fdividef(e - 1.f, e + 1.f);
}

__global__ __launch_bounds__(256) void gru_rec_kernel(float* __restrict__ out) {
    __shared__ float4 hs4[HH];    // [k] -> h for batches b0..b0+3
    __shared__ float4 rhs4[HH];   // [k] -> r*h for batches b0..b0+3

    int j  = threadIdx.x;
    int b0 = blockIdx.x * 4;

    hs4[j] = make_float4(0.f, 0.f, 0.f, 0.f);
    __syncthreads();

    const float2* __restrict__ Wzr = g_Wzr;
    const float*  __restrict__ Wm  = g_Wm2;

    for (int t = 0; t < TT; t++) {
        const float* gx = g_Gx + ((size_t)t * BSZ + b0) * G3 + j;

        // independent-of-h loads issued early
        float gz0 = __ldg(gx);            float gz1 = __ldg(gx + G3);
        float gz2 = __ldg(gx + 2 * G3);   float gz3 = __ldg(gx + 3 * G3);
        float gr0 = __ldg(gx + HH);           float gr1 = __ldg(gx + G3 + HH);
        float gr2 = __ldg(gx + 2 * G3 + HH);  float gr3 = __ldg(gx + 3 * G3 + HH);

        float z0 = gz0, z1 = gz1, z2 = gz2, z3 = gz3;
        float r0 = gr0, r1 = gr1, r2 = gr2, r3 = gr3;

#pragma unroll 8
        for (int k = 0; k < HH; k++) {
            float2 w = __ldg(&Wzr[k * HH + j]);
            float4 h = hs4[k];
            z0 = fmaf(w.x, h.x, z0); z1 = fmaf(w.x, h.y, z1);
            z2 = fmaf(w.x, h.z, z2); z3 = fmaf(w.x, h.w, z3);
            r0 = fmaf(w.y, h.x, r0); r1 = fmaf(w.y, h.y, r1);
            r2 = fmaf(w.y, h.z, r2); r3 = fmaf(w.y, h.w, r3);
        }

        float4 hold = hs4[j];
        z0 = fast_sigmoid(z0); z1 = fast_sigmoid(z1);
        z2 = fast_sigmoid(z2); z3 = fast_sigmoid(z3);
        r0 = fast_sigmoid(r0); r1 = fast_sigmoid(r1);
        r2 = fast_sigmoid(r2); r3 = fast_sigmoid(r3);
        rhs4[j] = make_float4(r0 * hold.x, r1 * hold.y, r2 * hold.z, r3 * hold.w);
        __syncthreads();   // rhs published; phase-A hs reads done

        float m0 = __ldg(gx + 2 * HH);           float m1 = __ldg(gx + G3 + 2 * HH);
        float m2 = __ldg(gx + 2 * G3 + 2 * HH);  float m3 = __ldg(gx + 3 * G3 + 2 * HH);

#pragma unroll 8
        for (int k = 0; k < HH; k++) {
            float wm = __ldg(&Wm[k * HH + j]);
            float4 rh = rhs4[k];
            m0 = fmaf(wm, rh.x, m0); m1 = fmaf(wm, rh.y, m1);
            m2 = fmaf(wm, rh.z, m2); m3 = fmaf(wm, rh.w, m3);
        }

        float hn0 = fmaf(z0, fast_tanh(m0) - hold.x, hold.x);
        float hn1 = fmaf(z1, fast_tanh(m1) - hold.y, hold.y);
        float hn2 = fmaf(z2, fast_tanh(m2) - hold.z, hold.z);
        float hn3 = fmaf(z3, fast_tanh(m3) - hold.w, hold.w);

        hs4[j] = make_float4(hn0, hn1, hn2, hn3);

        float* op = out + ((size_t)b0 * TT + t) * HH + j;
        op[0]                       = hn0;
        op[(size_t)TT * HH]         = hn1;
        op[(size_t)2 * TT * HH]     = hn2;
        op[(size_t)3 * TT * HH]     = hn3;
        __syncthreads();   // hs published for next step; rhs reads done
    }
}

// ---------------------------------------------------------------------------
// Launch
// ---------------------------------------------------------------------------
extern "C" void kernel_launch(void* const* d_in, const int* in_sizes, int n_in,
                              void* d_out, int out_size) {
    const float* emb = (const float*)d_in[0];
    const float* Wz  = (const float*)d_in[1];
    const float* bz  = (const float*)d_in[2];
    const float* Wr  = (const float*)d_in[3];
    const float* br  = (const float*)d_in[4];
    const float* Wm  = (const float*)d_in[5];
    const float* bm  = (const float*)d_in[6];
    float* out = (float*)d_out;

    prep_kernel<<<(KH * G3 + 255) / 256, 256>>>(Wz, bz, Wr, br, Wm, bm);
    gemm_x_kernel<<<dim3(G3 / BN, (BSZ * TT) / BM), 256>>>(emb);
    gru_rec_kernel<<<BSZ / 4, 256>>>(out);
}

// round 5
// speedup vs baseline: 4.8942x; 4.5223x over previous
#include <cuda_runtime.h>
#include <math.h>
#include <stdint.h>

// Problem constants
#define BSZ 256     // batch
#define TT  512     // time steps
#define EE  256     // embedding dim
#define HH  256     // hidden dim
#define KH  512     // E + H
#define G3  768     // 3 * H (z, r, m)

typedef unsigned long long u64;

// Scratch (device globals: allocation-free rule)
__device__ float  g_WT[EE * G3];                   // transposed weights for x-GEMM (rows k<EE)
__device__ float  g_bias[G3];
__device__ float2 g_Wzr[HH * HH];                  // recurrent z/r interleaved: [k][j] -> (Wz[j][E+k], Wr[j][E+k])
__device__ float  g_Wm2[HH * HH];                  // recurrent m:               [k][j] ->  Wm[j][E+k]
__device__ float  g_Gx[(size_t)BSZ * TT * G3];     // precomputed x-part + bias, layout [t][b][3H]

// ---------------------------------------------------------------------------
// PTX helpers: packed f32x2 math, DSMEM, cluster sync
// ---------------------------------------------------------------------------
__device__ __forceinline__ u64 pack2(float lo, float hi) {
    u64 r; asm("mov.b64 %0, {%1, %2};" : "=l"(r) : "f"(lo), "f"(hi)); return r;
}
__device__ __forceinline__ float2 unpack2(u64 v) {
    float2 r; asm("mov.b64 {%0, %1}, %2;" : "=f"(r.x), "=f"(r.y) : "l"(v)); return r;
}
__device__ __forceinline__ void ffma2(u64& d, u64 a, u64 b) {
    asm("fma.rn.f32x2 %0, %1, %2, %0;" : "+l"(d) : "l"(a), "l"(b));
}
__device__ __forceinline__ u64 add2(u64 a, u64 b) {
    u64 r; asm("add.rn.f32x2 %0, %1, %2;" : "=l"(r) : "l"(a), "l"(b)); return r;
}
__device__ __forceinline__ uint32_t smem_u32(const void* p) {
    uint32_t a;
    asm("{ .reg .u64 t; cvta.to.shared.u64 t, %1; cvt.u32.u64 %0, t; }" : "=r"(a) : "l"(p));
    return a;
}
__device__ __forceinline__ uint32_t mapa_u32(uint32_t a, uint32_t rank) {
    uint32_t r; asm("mapa.shared::cluster.u32 %0, %1, %2;" : "=r"(r) : "r"(a), "r"(rank)); return r;
}
__device__ __forceinline__ void st_cluster_b64(uint32_t a, u64 v) {
    asm volatile("st.shared::cluster.b64 [%0], %1;" :: "r"(a), "l"(v) : "memory");
}
#define CLUSTER_SYNC() do { \
    asm volatile("barrier.cluster.arrive.aligned;" ::: "memory"); \
    asm volatile("barrier.cluster.wait.aligned;"   ::: "memory"); \
} while (0)

__device__ __forceinline__ float fast_sigmoid(float x) {
    float e = __expf(-x);
    return __fdividef(1.f, 1.f + e);
}
__device__ __forceinline__ float fast_tanh(float x) {
    float e = __expf(2.f * x);
    return __fdividef(e - 1.f, e + 1.f);
}

// ---------------------------------------------------------------------------
// Kernel 1: weight transpose + bias concat + recurrent repack
// ---------------------------------------------------------------------------
__global__ void prep_kernel(const float* __restrict__ Wz, const float* __restrict__ bz,
                            const float* __restrict__ Wr, const float* __restrict__ br,
                            const float* __restrict__ Wm, const float* __restrict__ bm) {
    int idx = blockIdx.x * blockDim.x + threadIdx.x;
    if (idx < EE * G3) {                 // GEMM weights, rows k < EE
        int k  = idx / G3;
        int gj = idx - k * G3;
        int g  = gj >> 8;
        int jj = gj & 255;
        const float* W = (g == 0) ? Wz : (g == 1) ? Wr : Wm;
        g_WT[idx] = W[jj * KH + k];
    }
    if (idx < HH * HH) {                 // recurrent repack (k = reduction idx, j = unit)
        int k = idx >> 8;
        int j = idx & 255;
        g_Wzr[idx] = make_float2(Wz[j * KH + EE + k], Wr[j * KH + EE + k]);
        g_Wm2[idx] = Wm[j * KH + EE + k];
    }
    if (idx < G3) {
        int g  = idx >> 8;
        int jj = idx & 255;
        const float* bb = (g == 0) ? bz : (g == 1) ? br : bm;
        g_bias[idx] = bb[jj];
    }
}

// ---------------------------------------------------------------------------
// Kernel 2: Gx[t][b][gj] = emb[b][t][:] . WT[:E][gj] + bias[gj]
// Tiled fp32 GEMM: M = T*B (m = t*256 + b), N = 768, K = 256
// ---------------------------------------------------------------------------
#define BM 128
#define BN 128
#define BK 8

__global__ __launch_bounds__(256) void gemm_x_kernel(const float* __restrict__ emb) {
    __shared__ float As[BK][BM];
    __shared__ float Bs[BK][BN];

    int tid = threadIdx.x;
    int m0 = blockIdx.y * BM;
    int n0 = blockIdx.x * BN;

    int tx = tid & 15;
    int ty = tid >> 4;

    int arow = tid >> 1;
    int akq  = (tid & 1) << 2;
    int m    = m0 + arow;
    int bidx = m & (BSZ - 1);
    int tidx = m >> 8;
    const float* aptr = emb + ((size_t)bidx * TT + tidx) * EE + akq;

    int bkr = tid >> 5;
    int bnq = (tid & 31) << 2;
    const float* bptr = g_WT + (size_t)bkr * G3 + n0 + bnq;

    float acc[8][8];
#pragma unroll
    for (int i = 0; i < 8; i++)
#pragma unroll
        for (int jj = 0; jj < 8; jj++) acc[i][jj] = 0.f;

    for (int k0 = 0; k0 < EE; k0 += BK) {
        float4 av = *(const float4*)(aptr + k0);
        float4 bv = *(const float4*)(bptr + (size_t)k0 * G3);

        As[akq + 0][arow] = av.x;
        As[akq + 1][arow] = av.y;
        As[akq + 2][arow] = av.z;
        As[akq + 3][arow] = av.w;
        *(float4*)(&Bs[bkr][bnq]) = bv;
        __syncthreads();

#pragma unroll
        for (int kk = 0; kk < BK; kk++) {
            float a[8], b[8];
            *(float4*)(a)     = *(const float4*)(&As[kk][ty * 8]);
            *(float4*)(a + 4) = *(const float4*)(&As[kk][ty * 8 + 4]);
            *(float4*)(b)     = *(const float4*)(&Bs[kk][tx * 8]);
            *(float4*)(b + 4) = *(const float4*)(&Bs[kk][tx * 8 + 4]);
#pragma unroll
            for (int i = 0; i < 8; i++)
#pragma unroll
                for (int jj = 0; jj < 8; jj++)
                    acc[i][jj] = fmaf(a[i], b[jj], acc[i][jj]);
        }
        __syncthreads();
    }

    float biasv[8];
    *(float4*)(biasv)     = *(const float4*)(&g_bias[n0 + tx * 8]);
    *(float4*)(biasv + 4) = *(const float4*)(&g_bias[n0 + tx * 8 + 4]);

#pragma unroll
    for (int i = 0; i < 8; i++) {
        int mm = m0 + ty * 8 + i;
        float* gp = g_Gx + (size_t)mm * G3 + n0 + tx * 8;
        float4 v0, v1;
        v0.x = acc[i][0] + biasv[0]; v0.y = acc[i][1] + biasv[1];
        v0.z = acc[i][2] + biasv[2]; v0.w = acc[i][3] + biasv[3];
        v1.x = acc[i][4] + biasv[4]; v1.y = acc[i][5] + biasv[5];
        v1.z = acc[i][6] + biasv[6]; v1.w = acc[i][7] + biasv[7];
        *(float4*)(gp)     = v0;
        *(float4*)(gp + 4) = v1;
    }
}

// ---------------------------------------------------------------------------
// Kernel 3: recurrent part, cluster-of-4 version.
// - cluster = 8 batches; each CTA owns j-slice [rank*64, rank*64+64)
// - per-CTA weight slice (192KB) staged in SMEM once (no L2 in steady state)
// - 256 threads = 64 jl x 4 k-slices: each weight read ONCE per step
// - f32x2 packed FMA: (z,r) in lanes for phase A; batch-pairs for phase B
// - h / r*h replicated per CTA, exchanged via DSMEM + 2 cluster barriers/step
// SMEM layout (bytes):
//   wzr_s : 256k x 64jl float2 = 131072
//   wm_s  : 256k x 64jl float  =  65536
//   h_s   : 256j x 8b   float  =   8192   (batch-minor, full h replicated)
//   rh_s  : 256j x 8b   float  =   8192
//   p_s   : 4ks x 64jl x 9 u64 =  18432   (partials, stride-9 anti-conflict)
// total = 231424 <= 232448 (227KB cap)
// ---------------------------------------------------------------------------
#define SM_WZR 0
#define SM_WM  131072
#define SM_H   196608
#define SM_RH  204800
#define SM_P   212992
#define SM_TOTAL 231424

__global__ void __launch_bounds__(256, 1) __cluster_dims__(4, 1, 1)
gru_rec_kernel(float* __restrict__ out) {
    extern __shared__ char smem_raw[];
    float2* wzr_s = (float2*)(smem_raw + SM_WZR);
    float*  wm_s  = (float*)(smem_raw + SM_WM);
    float*  h_s   = (float*)(smem_raw + SM_H);
    float*  rh_s  = (float*)(smem_raw + SM_RH);
    u64*    p_s   = (u64*)(smem_raw + SM_P);

    int tid   = threadIdx.x;
    int jl    = tid & 63;        // j within slice
    int ksub  = tid >> 6;        // k-slice (phase role) == batch-pair (reduce role)
    int crank = blockIdx.x & 3;
    int b0g   = (blockIdx.x >> 2) * 8;
    int jg    = crank * 64 + jl;

    // Stage weight slice: wzr_s[k*64+jl] = g_Wzr[k][crank*64+jl], same for wm
    for (int i = tid; i < HH * 64; i += 256) {
        int k  = i >> 6;
        int j2 = (i & 63) + crank * 64;
        wzr_s[i] = g_Wzr[k * HH + j2];
        wm_s[i]  = g_Wm2[k * HH + j2];
    }
    for (int i = tid; i < HH * 8; i += 256) h_s[i] = 0.f;
    __syncthreads();
    CLUSTER_SYNC();

    // DSMEM destination bases (computed once)
    uint32_t rh_local = smem_u32(rh_s);
    uint32_t h_local  = smem_u32(h_s);
    uint32_t rh_dst[4], h_dst[4];
#pragma unroll
    for (int d = 0; d < 4; d++) {
        rh_dst[d] = mapa_u32(rh_local, (uint32_t)d);
        h_dst[d]  = mapa_u32(h_local,  (uint32_t)d);
    }
    uint32_t off_pair = (uint32_t)(jg * 8 + 2 * ksub) * 4;   // byte offset of this thread's (jg, batch-pair)

    int k0 = ksub * 64;

    for (int t = 0; t < TT; t++) {
        // Prefetch Gx for this thread's reduce role (batch pair 2*ksub, 2*ksub+1 @ jg)
        const float* gxb = g_Gx + ((size_t)t * BSZ + b0g + 2 * ksub) * G3 + jg;
        float gz0 = __ldg(gxb);            float gr0 = __ldg(gxb + HH);
        float gm0 = __ldg(gxb + 2 * HH);
        float gz1 = __ldg(gxb + G3);       float gr1 = __ldg(gxb + G3 + HH);
        float gm1 = __ldg(gxb + G3 + 2 * HH);

        // -------- Phase A: partial z/r dots over this thread's k-slice --------
        u64 az0 = 0, az1 = 0, az2 = 0, az3 = 0;
        u64 ar0 = 0, ar1 = 0, ar2 = 0, ar3 = 0;
#pragma unroll 4
        for (int kk = 0; kk < 64; kk++) {
            int k = k0 + kk;
            float2 w = wzr_s[k * 64 + jl];
            u64 wzz = pack2(w.x, w.x);
            u64 wrr = pack2(w.y, w.y);
            ulonglong2 ha = *(const ulonglong2*)(h_s + k * 8);      // (h0,h1),(h2,h3)
            ulonglong2 hb = *(const ulonglong2*)(h_s + k * 8 + 4);  // (h4,h5),(h6,h7)
            ffma2(az0, wzz, ha.x); ffma2(az1, wzz, ha.y);
            ffma2(az2, wzz, hb.x); ffma2(az3, wzz, hb.y);
            ffma2(ar0, wrr, ha.x); ffma2(ar1, wrr, ha.y);
            ffma2(ar2, wrr, hb.x); ffma2(ar3, wrr, hb.y);
        }
        {
            u64* pr = p_s + (ksub * 64 + jl) * 9;
            pr[0] = az0; pr[1] = az1; pr[2] = az2; pr[3] = az3;
            pr[4] = ar0; pr[5] = ar1; pr[6] = ar2; pr[7] = ar3;
        }
        __syncthreads();

        // -------- Reduce A: sum 4 k-slices, activations, publish r*h --------
        u64 zz = 0, rr = 0;
#pragma unroll
        for (int ks = 0; ks < 4; ks++) {
            const u64* pr = p_s + (ks * 64 + jl) * 9;
            zz = add2(zz, pr[ksub]);
            rr = add2(rr, pr[4 + ksub]);
        }
        float2 zf = unpack2(zz), rf = unpack2(rr);
        float z0 = fast_sigmoid(zf.x + gz0);
        float z1 = fast_sigmoid(zf.y + gz1);
        float r0 = fast_sigmoid(rf.x + gr0);
        float r1 = fast_sigmoid(rf.y + gr1);
        float2 hold = *(const float2*)(h_s + jg * 8 + 2 * ksub);
        u64 rhp = pack2(r0 * hold.x, r1 * hold.y);
#pragma unroll
        for (int d = 0; d < 4; d++) st_cluster_b64(rh_dst[d] + off_pair, rhp);
        CLUSTER_SYNC();

        // -------- Phase B: partial m dots over k-slice against full r*h --------
        u64 am0 = 0, am1 = 0, am2 = 0, am3 = 0;
#pragma unroll 4
        for (int kk = 0; kk < 64; kk++) {
            int k = k0 + kk;
            float wm = wm_s[k * 64 + jl];
            u64 wmm = pack2(wm, wm);
            ulonglong2 ra = *(const ulonglong2*)(rh_s + k * 8);
            ulonglong2 rb = *(const ulonglong2*)(rh_s + k * 8 + 4);
            ffma2(am0, wmm, ra.x); ffma2(am1, wmm, ra.y);
            ffma2(am2, wmm, rb.x); ffma2(am3, wmm, rb.y);
        }
        {
            u64* pr = p_s + (ksub * 64 + jl) * 9;
            pr[0] = am0; pr[1] = am1; pr[2] = am2; pr[3] = am3;
        }
        __syncthreads();

        // -------- Reduce B: tanh, blend, publish h_new, store output --------
        u64 mm = 0;
#pragma unroll
        for (int ks = 0; ks < 4; ks++)
            mm = add2(mm, p_s[(ks * 64 + jl) * 9 + ksub]);
        float2 mf = unpack2(mm);
        float hc0 = fast_tanh(mf.x + gm0);
        float hc1 = fast_tanh(mf.y + gm1);
        float hn0 = fmaf(z0, hc0 - hold.x, hold.x);
        float hn1 = fmaf(z1, hc1 - hold.y, hold.y);
        u64 hp = pack2(hn0, hn1);
#pragma unroll
        for (int d = 0; d < 4; d++) st_cluster_b64(h_dst[d] + off_pair, hp);

        float* op = out + ((size_t)(b0g + 2 * ksub) * TT + t) * HH + jg;
        op[0]               = hn0;
        op[(size_t)TT * HH] = hn1;
        CLUSTER_SYNC();
    }
}

// ---------------------------------------------------------------------------
// Launch
// ---------------------------------------------------------------------------
extern "C" void kernel_launch(void* const* d_in, const int* in_sizes, int n_in,
                              void* d_out, int out_size) {
    const float* emb = (const float*)d_in[0];
    const float* Wz  = (const float*)d_in[1];
    const float* bz  = (const float*)d_in[2];
    const float* Wr  = (const float*)d_in[3];
    const float* br  = (const float*)d_in[4];
    const float* Wm  = (const float*)d_in[5];
    const float* bm  = (const float*)d_in[6];
    float* out = (float*)d_out;

    cudaFuncSetAttribute(gru_rec_kernel,
                         cudaFuncAttributeMaxDynamicSharedMemorySize, SM_TOTAL);

    prep_kernel<<<(EE * G3 + 255) / 256, 256>>>(Wz, bz, Wr, br, Wm, bm);
    gemm_x_kernel<<<dim3(G3 / BN, (BSZ * TT) / BM), 256>>>(emb);
    gru_rec_kernel<<<128, 256, SM_TOTAL>>>(out);
}

// round 7
// speedup vs baseline: 5.7074x; 1.1662x over previous
#include <cuda_runtime.h>
#include <cuda_bf16.h>
#include <math.h>
#include <stdint.h>

// Problem constants
#define BSZ 256     // batch
#define TT  512     // time steps
#define EE  256     // embedding dim
#define HH  256     // hidden dim
#define KH  512     // E + H
#define G3  768     // 3 * H (z, r, m)
#define MTOT (BSZ * TT)   // 131072 GEMM rows, m = t*256 + b

typedef unsigned long long u64;

// Scratch (device globals: allocation-free rule)
__device__ float        g_bias[G3];
__device__ float2       g_Wzr[HH * HH];              // recurrent z/r interleaved
__device__ float        g_Wm2[HH * HH];              // recurrent m
__device__ __nv_bfloat16 g_Bhi[G3 * EE];             // B row n=g*256+j, col k: bf16 hi of Wg[j][k]
__device__ __nv_bfloat16 g_Blo[G3 * EE];             // bf16 lo residual
__device__ __nv_bfloat16 g_Ahi[(size_t)MTOT * EE];   // A row m=t*256+b, col k: bf16 hi of emb[b][t][k]
__device__ __nv_bfloat16 g_Alo[(size_t)MTOT * EE];
__device__ float        g_Gx[(size_t)MTOT * G3];     // x-part + bias, layout [t][b][3H]

// ---------------------------------------------------------------------------
// PTX helpers
// ---------------------------------------------------------------------------
__device__ __forceinline__ u64 pack2(float lo, float hi) {
    u64 r; asm("mov.b64 %0, {%1, %2};" : "=l"(r) : "f"(lo), "f"(hi)); return r;
}
__device__ __forceinline__ float2 unpack2(u64 v) {
    float2 r; asm("mov.b64 {%0, %1}, %2;" : "=f"(r.x), "=f"(r.y) : "l"(v)); return r;
}
__device__ __forceinline__ void ffma2(u64& d, u64 a, u64 b) {
    asm("fma.rn.f32x2 %0, %1, %2, %0;" : "+l"(d) : "l"(a), "l"(b));
}
__device__ __forceinline__ u64 add2(u64 a, u64 b) {
    u64 r; asm("add.rn.f32x2 %0, %1, %2;" : "=l"(r) : "l"(a), "l"(b)); return r;
}
__device__ __forceinline__ uint32_t smem_u32(const void* p) {
    uint32_t a;
    asm("{ .reg .u64 t; cvta.to.shared.u64 t, %1; cvt.u32.u64 %0, t; }" : "=r"(a) : "l"(p));
    return a;
}
__device__ __forceinline__ uint32_t mapa_u32(uint32_t a, uint32_t rank) {
    uint32_t r; asm("mapa.shared::cluster.u32 %0, %1, %2;" : "=r"(r) : "r"(a), "r"(rank)); return r;
}
__device__ __forceinline__ void st_cluster_b64(uint32_t a, u64 v) {
    asm volatile("st.shared::cluster.b64 [%0], %1;" :: "r"(a), "l"(v) : "memory");
}
#define CLUSTER_SYNC() do { \
    asm volatile("barrier.cluster.arrive.aligned;" ::: "memory"); \
    asm volatile("barrier.cluster.wait.aligned;"   ::: "memory"); \
} while (0)

__device__ __forceinline__ float fast_sigmoid(float x) {
    float e = __expf(-x);
    return __fdividef(1.f, 1.f + e);
}
__device__ __forceinline__ float fast_tanh(float x) {
    float e = __expf(2.f * x);
    return __fdividef(e - 1.f, e + 1.f);
}

// ---- warp-level MMA helpers (sm_80+ path, valid on base sm_103 target) ----
__device__ __forceinline__ void ldsm_x4(uint32_t* r, uint32_t addr) {
    asm volatile("ldmatrix.sync.aligned.m8n8.x4.shared.b16 {%0,%1,%2,%3}, [%4];"
        : "=r"(r[0]), "=r"(r[1]), "=r"(r[2]), "=r"(r[3]) : "r"(addr));
}
__device__ __forceinline__ void ldsm_x2(uint32_t* r, uint32_t addr) {
    asm volatile("ldmatrix.sync.aligned.m8n8.x2.shared.b16 {%0,%1}, [%2];"
        : "=r"(r[0]), "=r"(r[1]) : "r"(addr));
}
__device__ __forceinline__ void mma16816(float* d, const uint32_t* a, const uint32_t* b) {
    asm volatile(
        "mma.sync.aligned.m16n8k16.row.col.f32.bf16.bf16.f32 "
        "{%0,%1,%2,%3}, {%4,%5,%6,%7}, {%8,%9}, {%0,%1,%2,%3};"
        : "+f"(d[0]), "+f"(d[1]), "+f"(d[2]), "+f"(d[3])
        : "r"(a[0]), "r"(a[1]), "r"(a[2]), "r"(a[3]), "r"(b[0]), "r"(b[1]));
}

// ---------------------------------------------------------------------------
// Kernel 1: bias + recurrent repack + B hi/lo bf16 split
// ---------------------------------------------------------------------------
__global__ void prep_kernel(const float* __restrict__ Wz, const float* __restrict__ bz,
                            const float* __restrict__ Wr, const float* __restrict__ br,
                            const float* __restrict__ Wm, const float* __restrict__ bm) {
    int idx = blockIdx.x * blockDim.x + threadIdx.x;
    if (idx < G3 * EE) {                 // B split: row n = g*256+j, col k
        int n = idx >> 8;
        int k = idx & 255;
        int g = n >> 8;
        int j = n & 255;
        const float* W = (g == 0) ? Wz : (g == 1) ? Wr : Wm;
        float v = W[j * KH + k];
        __nv_bfloat16 hi = __float2bfloat16(v);
        g_Bhi[idx] = hi;
        g_Blo[idx] = __float2bfloat16(v - __bfloat162float(hi));
    }
    if (idx < HH * HH) {                 // recurrent repack
        int k = idx >> 8;
        int j = idx & 255;
        g_Wzr[idx] = make_float2(Wz[j * KH + EE + k], Wr[j * KH + EE + k]);
        g_Wm2[idx] = Wm[j * KH + EE + k];
    }
    if (idx < G3) {
        int g  = idx >> 8;
        int jj = idx & 255;
        const float* bb = (g == 0) ? bz : (g == 1) ? br : bm;
        g_bias[idx] = bb[jj];
    }
}

// ---------------------------------------------------------------------------
// Kernel 1b: A hi/lo bf16 split, row m = t*256+b, col k (from emb[b][t][k])
// ---------------------------------------------------------------------------
__global__ __launch_bounds__(256) void conv_a_kernel(const float* __restrict__ emb) {
    size_t q = (size_t)blockIdx.x * 256 + threadIdx.x;   // quad index
    size_t m = q >> 6;
    int kq = (int)(q & 63) * 4;
    int b = (int)(m & 255);
    int t = (int)(m >> 8);
    float4 v = *(const float4*)(emb + ((size_t)b * TT + t) * EE + kq);
    __nv_bfloat16 h0 = __float2bfloat16(v.x), h1 = __float2bfloat16(v.y);
    __nv_bfloat16 h2 = __float2bfloat16(v.z), h3 = __float2bfloat16(v.w);
    __nv_bfloat16 hv[4] = {h0, h1, h2, h3};
    __nv_bfloat16 lv[4] = {
        __float2bfloat16(v.x - __bfloat162float(h0)),
        __float2bfloat16(v.y - __bfloat162float(h1)),
        __float2bfloat16(v.z - __bfloat162float(h2)),
        __float2bfloat16(v.w - __bfloat162float(h3))};
    *(uint2*)(g_Ahi + m * EE + kq) = *(const uint2*)hv;
    *(uint2*)(g_Alo + m * EE + kq) = *(const uint2*)lv;
}

// ---------------------------------------------------------------------------
// Kernel 2: split-bf16 GEMM via mma.sync (m16n8k16).
// 1024 CTAs x 256 thr (8 warps, 4x2 -> warp tile 32M x 64N).
// A (128 rows x K=256, hi+lo) SMEM-resident; loops 6 N-tiles of 128 with
// B chunks (128n x 128k, hi+lo) streamed from L2.
// D(fp32) += Ahi*Bhi + Ahi*Blo + Alo*Bhi  (lo*lo dropped, ~2^-18 rel)
// SMEM strides padded by 8 halves -> 4-bank row shift -> conflict-free ldmatrix
// ---------------------------------------------------------------------------
#define LDA 264                          // A smem row stride (halves): 256 + 8
#define LDB 136                          // B smem row stride (halves): 128 + 8
#define SA_HI 0
#define SA_LO (128 * LDA * 2)            //  67584
#define SB_HI (2 * 128 * LDA * 2)        // 135168
#define SB_LO (SB_HI + 128 * LDB * 2)    // 169984
#define GEMM_SMEM (SB_LO + 128 * LDB * 2) // 204800

__global__ void __launch_bounds__(256, 1) gemm_mma_kernel() {
    extern __shared__ char smem[];
    uint32_t sbase = smem_u32(smem);
    int tid  = threadIdx.x;
    int warp = tid >> 5;
    int lane = tid & 31;
    int m0 = blockIdx.x * 128;

    int wm = (warp >> 1) * 32;           // warp M offset (0,32,64,96)
    int wn = (warp & 1) * 64;            // warp N offset (0,64)

    // ---- Load A tile (full K=256, hi+lo) ----
    for (int u = tid; u < 128 * 32; u += 256) {      // 32 chunks of 8 halves per row
        int row = u >> 5;
        int c   = u & 31;
        size_t src = (size_t)(m0 + row) * EE + c * 8;
        int dst = (row * LDA + c * 8) * 2;
        *(uint4*)(smem + SA_HI + dst) = *(const uint4*)(g_Ahi + src);
        *(uint4*)(smem + SA_LO + dst) = *(const uint4*)(g_Alo + src);
    }

    // Fragment base addresses (lane-dependent parts)
    uint32_t a_row = (uint32_t)(wm + (lane & 15));           // + mi*16
    uint32_t a_coff = (uint32_t)((lane >> 4) * 8);           // + kcol
    uint32_t b_row = (uint32_t)(wn + (lane & 7));            // + ni*8
    uint32_t b_coff = (uint32_t)(((lane >> 3) & 1) * 8);     // + k16*16

    for (int nj = 0; nj < 6; nj++) {
        float acc[2][8][4];
#pragma unroll
        for (int mi = 0; mi < 2; mi++)
#pragma unroll
            for (int ni = 0; ni < 8; ni++)
#pragma unroll
                for (int c = 0; c < 4; c++) acc[mi][ni][c] = 0.f;

        for (int kt = 0; kt < 2; kt++) {
            __syncthreads();   // prior MMA reads of B done before overwrite
            // ---- Load B chunk (128n x 128k, hi+lo) ----
            for (int u = tid; u < 128 * 16; u += 256) {
                int row = u >> 4;
                int c   = u & 15;
                size_t src = (size_t)(nj * 128 + row) * EE + kt * 128 + c * 8;
                int dst = (row * LDB + c * 8) * 2;
                *(uint4*)(smem + SB_HI + dst) = *(const uint4*)(g_Bhi + src);
                *(uint4*)(smem + SB_LO + dst) = *(const uint4*)(g_Blo + src);
            }
            __syncthreads();

#pragma unroll
            for (int k16 = 0; k16 < 8; k16++) {
                int kA = kt * 128 + k16 * 16;      // A col within full K
                int kB = k16 * 16;                 // B col within chunk

                uint32_t aH[2][4], aL[2][4];
#pragma unroll
                for (int mi = 0; mi < 2; mi++) {
                    uint32_t off = ((a_row + mi * 16) * LDA + kA + a_coff) * 2;
                    ldsm_x4(aH[mi], sbase + SA_HI + off);
                    ldsm_x4(aL[mi], sbase + SA_LO + off);
                }
                uint32_t bH[8][2], bL[8][2];
#pragma unroll
                for (int ni = 0; ni < 8; ni++) {
                    uint32_t off = ((b_row + ni * 8) * LDB + kB + b_coff) * 2;
                    ldsm_x2(bH[ni], sbase + SB_HI + off);
                    ldsm_x2(bL[ni], sbase + SB_LO + off);
                }
#pragma unroll
                for (int mi = 0; mi < 2; mi++)
#pragma unroll
                    for (int ni = 0; ni < 8; ni++) {
                        mma16816(acc[mi][ni], aH[mi], bH[ni]);
                        mma16816(acc[mi][ni], aH[mi], bL[ni]);
                        mma16816(acc[mi][ni], aL[mi], bH[ni]);
                    }
            }
        }

        // ---- Epilogue: acc + bias -> g_Gx (registers only, no smem) ----
        int row0 = m0 + wm + (lane >> 2);
#pragma unroll
        for (int mi = 0; mi < 2; mi++) {
#pragma unroll
            for (int ni = 0; ni < 8; ni++) {
                int n = nj * 128 + wn + ni * 8 + 2 * (lane & 3);
                float b0 = __ldg(g_bias + n);
                float b1 = __ldg(g_bias + n + 1);
                float2 v0 = make_float2(acc[mi][ni][0] + b0, acc[mi][ni][1] + b1);
                float2 v1 = make_float2(acc[mi][ni][2] + b0, acc[mi][ni][3] + b1);
                *(float2*)(g_Gx + (size_t)(row0 + mi * 16) * G3 + n)     = v0;
                *(float2*)(g_Gx + (size_t)(row0 + mi * 16 + 8) * G3 + n) = v1;
            }
        }
    }
}

// ---------------------------------------------------------------------------
// Kernel 3: recurrent part, cluster-of-4 (unchanged from R5)
// ---------------------------------------------------------------------------
#define SM_WZR 0
#define SM_WM  131072
#define SM_H   196608
#define SM_RH  204800
#define SM_P   212992
#define SM_TOTAL 231424

__global__ void __launch_bounds__(256, 1) __cluster_dims__(4, 1, 1)
gru_rec_kernel(float* __restrict__ out) {
    extern __shared__ char smem_raw[];
    float2* wzr_s = (float2*)(smem_raw + SM_WZR);
    float*  wm_s  = (float*)(smem_raw + SM_WM);
    float*  h_s   = (float*)(smem_raw + SM_H);
    float*  rh_s  = (float*)(smem_raw + SM_RH);
    u64*    p_s   = (u64*)(smem_raw + SM_P);

    int tid   = threadIdx.x;
    int jl    = tid & 63;
    int ksub  = tid >> 6;
    int crank = blockIdx.x & 3;
    int b0g   = (blockIdx.x >> 2) * 8;
    int jg    = crank * 64 + jl;

    for (int i = tid; i < HH * 64; i += 256) {
        int k  = i >> 6;
        int j2 = (i & 63) + crank * 64;
        wzr_s[i] = g_Wzr[k * HH + j2];
        wm_s[i]  = g_Wm2[k * HH + j2];
    }
    for (int i = tid; i < HH * 8; i += 256) h_s[i] = 0.f;
    __syncthreads();
    CLUSTER_SYNC();

    uint32_t rh_local = smem_u32(rh_s);
    uint32_t h_local  = smem_u32(h_s);
    uint32_t rh_dst[4], h_dst[4];
#pragma unroll
    for (int d = 0; d < 4; d++) {
        rh_dst[d] = mapa_u32(rh_local, (uint32_t)d);
        h_dst[d]  = mapa_u32(h_local,  (uint32_t)d);
    }
    uint32_t off_pair = (uint32_t)(jg * 8 + 2 * ksub) * 4;

    int k0 = ksub * 64;

    for (int t = 0; t < TT; t++) {
        const float* gxb = g_Gx + ((size_t)t * BSZ + b0g + 2 * ksub) * G3 + jg;
        float gz0 = __ldg(gxb);            float gr0 = __ldg(gxb + HH);
        float gm0 = __ldg(gxb + 2 * HH);
        float gz1 = __ldg(gxb + G3);       float gr1 = __ldg(gxb + G3 + HH);
        float gm1 = __ldg(gxb + G3 + 2 * HH);

        u64 az0 = 0, az1 = 0, az2 = 0, az3 = 0;
        u64 ar0 = 0, ar1 = 0, ar2 = 0, ar3 = 0;
#pragma unroll 4
        for (int kk = 0; kk < 64; kk++) {
            int k = k0 + kk;
            float2 w = wzr_s[k * 64 + jl];
            u64 wzz = pack2(w.x, w.x);
            u64 wrr = pack2(w.y, w.y);
            ulonglong2 ha = *(const ulonglong2*)(h_s + k * 8);
            ulonglong2 hb = *(const ulonglong2*)(h_s + k * 8 + 4);
            ffma2(az0, wzz, ha.x); ffma2(az1, wzz, ha.y);
            ffma2(az2, wzz, hb.x); ffma2(az3, wzz, hb.y);
            ffma2(ar0, wrr, ha.x); ffma2(ar1, wrr, ha.y);
            ffma2(ar2, wrr, hb.x); ffma2(ar3, wrr, hb.y);
        }
        {
            u64* pr = p_s + (ksub * 64 + jl) * 9;
            pr[0] = az0; pr[1] = az1; pr[2] = az2; pr[3] = az3;
            pr[4] = ar0; pr[5] = ar1; pr[6] = ar2; pr[7] = ar3;
        }
        __syncthreads();

        u64 zz = 0, rr = 0;
#pragma unroll
        for (int ks = 0; ks < 4; ks++) {
            const u64* pr = p_s + (ks * 64 + jl) * 9;
            zz = add2(zz, pr[ksub]);
            rr = add2(rr, pr[4 + ksub]);
        }
        float2 zf = unpack2(zz), rf = unpack2(rr);
        float z0 = fast_sigmoid(zf.x + gz0);
        float z1 = fast_sigmoid(zf.y + gz1);
        float r0 = fast_sigmoid(rf.x + gr0);
        float r1 = fast_sigmoid(rf.y + gr1);
        float2 hold = *(const float2*)(h_s + jg * 8 + 2 * ksub);
        u64 rhp = pack2(r0 * hold.x, r1 * hold.y);
#pragma unroll
        for (int d = 0; d < 4; d++) st_cluster_b64(rh_dst[d] + off_pair, rhp);
        CLUSTER_SYNC();

        u64 am0 = 0, am1 = 0, am2 = 0, am3 = 0;
#pragma unroll 4
        for (int kk = 0; kk < 64; kk++) {
            int k = k0 + kk;
            float wm = wm_s[k * 64 + jl];
            u64 wmm = pack2(wm, wm);
            ulonglong2 ra = *(const ulonglong2*)(rh_s + k * 8);
            ulonglong2 rb = *(const ulonglong2*)(rh_s + k * 8 + 4);
            ffma2(am0, wmm, ra.x); ffma2(am1, wmm, ra.y);
            ffma2(am2, wmm, rb.x); ffma2(am3, wmm, rb.y);
        }
        {
            u64* pr = p_s + (ksub * 64 + jl) * 9;
            pr[0] = am0; pr[1] = am1; pr[2] = am2; pr[3] = am3;
        }
        __syncthreads();

        u64 mm = 0;
#pragma unroll
        for (int ks = 0; ks < 4; ks++)
            mm = add2(mm, p_s[(ks * 64 + jl) * 9 + ksub]);
        float2 mf = unpack2(mm);
        float hc0 = fast_tanh(mf.x + gm0);
        float hc1 = fast_tanh(mf.y + gm1);
        float hn0 = fmaf(z0, hc0 - hold.x, hold.x);
        float hn1 = fmaf(z1, hc1 - hold.y, hold.y);
        u64 hp = pack2(hn0, hn1);
#pragma unroll
        for (int d = 0; d < 4; d++) st_cluster_b64(h_dst[d] + off_pair, hp);

        float* op = out + ((size_t)(b0g + 2 * ksub) * TT + t) * HH + jg;
        op[0]               = hn0;
        op[(size_t)TT * HH] = hn1;
        CLUSTER_SYNC();
    }
}

// ---------------------------------------------------------------------------
// Launch
// ---------------------------------------------------------------------------
extern "C" void kernel_launch(void* const* d_in, const int* in_sizes, int n_in,
                              void* d_out, int out_size) {
    const float* emb = (const float*)d_in[0];
    const float* Wz  = (const float*)d_in[1];
    const float* bz  = (const float*)d_in[2];
    const float* Wr  = (const float*)d_in[3];
    const float* br  = (const float*)d_in[4];
    const float* Wm  = (const float*)d_in[5];
    const float* bm  = (const float*)d_in[6];
    float* out = (float*)d_out;

    cudaFuncSetAttribute(gemm_mma_kernel,
                         cudaFuncAttributeMaxDynamicSharedMemorySize, GEMM_SMEM);
    cudaFuncSetAttribute(gru_rec_kernel,
                         cudaFuncAttributeMaxDynamicSharedMemorySize, SM_TOTAL);

    prep_kernel<<<(G3 * EE + 255) / 256, 256>>>(Wz, bz, Wr, br, Wm, bm);
    conv_a_kernel<<<(int)(((size_t)MTOT * EE / 4) / 256), 256>>>(emb);
    gemm_mma_kernel<<<MTOT / 128, 256, GEMM_SMEM>>>();
    gru_rec_kernel<<<128, 256, SM_TOTAL>>>(out);
}